// round 10
// baseline (speedup 1.0000x reference)
#include <cuda_runtime.h>
#include <cuda_fp16.h>
#include <cuda_bf16.h>
#include <mma.h>
#include <cstdint>
#include <cstddef>

using namespace nvcuda;

#define CC 256
#define PP 4096
#define NN 262144

// ---------------- scratch (device globals: no allocation allowed) ----------------
static __device__ float  g_G   [PP * CC];   // LN(segment mean of dg)
static __device__ float  g_ATT [PP * CC];   // attn (= residual)
static __device__ float  g_Y   [PP * CC];   // LN(attn)
static __device__ float  g_H   [PP * CC];   // relu(y@W1.T+b1)
static __device__ float  g_G2  [PP * CC];   // H@M1.T + ATT@Wf2.T + bias2
static __device__ float  g_WVO [CC * CC];   // out_proj_w @ Wv
static __device__ float  g_BVO [CC];        // out_proj_w @ bv + bo
static __device__ float  g_M1  [CC * CC];   // Wf2 @ l2w
static __device__ float  g_B2  [CC];        // Wf2 @ l2b + fuse_b
static __device__ __half g_WFh [CC * CC];   // fp16 W'[n,k] = node_w[k]*fuse_w1[n,k]
static __device__ float  g_U   [CC];        // rowsum(fp16 W')
static __device__ float  g_V   [CC];        // node_b @ fuse_w1.T
static __device__ __half g_OH  [(size_t)NN * CC];  // fp16 orig
static __device__ float  g_MU  [NN];        // per-row mean (fp32-exact)
static __device__ float  g_RS  [NN];        // per-row rstd

// ---------------- helpers ----------------
__device__ __forceinline__ uint32_t smem_u32(const void* p) {
    uint32_t a;
    asm("{ .reg .u64 t; cvta.to.shared.u64 t, %1; cvt.u32.u64 %0, t; }" : "=r"(a) : "l"(p));
    return a;
}
__device__ __forceinline__ void cp_async16(uint32_t smem, const void* gmem) {
    asm volatile("cp.async.cg.shared.global [%0], [%1], 16;\n" :: "r"(smem), "l"(gmem));
}
#define CP_COMMIT() asm volatile("cp.async.commit_group;\n" ::: "memory")
#define CP_WAIT(n)  asm volatile("cp.async.wait_group %0;\n" :: "n"(n) : "memory")

__device__ __forceinline__ void ldsm4(uint32_t& r0, uint32_t& r1, uint32_t& r2, uint32_t& r3,
                                      uint32_t addr) {
    asm volatile("ldmatrix.sync.aligned.m8n8.x4.shared.b16 {%0,%1,%2,%3}, [%4];"
                 : "=r"(r0), "=r"(r1), "=r"(r2), "=r"(r3) : "r"(addr));
}
__device__ __forceinline__ void mma_f16(float* d, uint32_t a0, uint32_t a1, uint32_t a2,
                                        uint32_t a3, uint32_t b0, uint32_t b1) {
    asm volatile(
        "mma.sync.aligned.m16n8k16.row.col.f32.f16.f16.f32 "
        "{%0,%1,%2,%3}, {%4,%5,%6,%7}, {%8,%9}, {%0,%1,%2,%3};"
        : "+f"(d[0]), "+f"(d[1]), "+f"(d[2]), "+f"(d[3])
        : "r"(a0), "r"(a1), "r"(a2), "r"(a3), "r"(b0), "r"(b1));
}

// 16B-chunk swizzle within a 64B row (conflict-free ldsm over 8 rows)
__device__ __forceinline__ uint32_t hswz(int row, int c16) {
    return (uint32_t)(row * 64 + (c16 ^ ((row >> 1) & 3)) * 16);
}

// ================ fused precompute + segment-mean kernel (launch 0) ================
__global__ void fused_pre_seg(
    const float* __restrict__ out_proj_w, const float* __restrict__ in_proj_w,
    const float* __restrict__ in_proj_b,  const float* __restrict__ out_proj_b,
    const float* __restrict__ fuse_w,     const float* __restrict__ l2w,
    const float* __restrict__ l2b,        const float* __restrict__ fuse_b,
    const float* __restrict__ node_w,     const float* __restrict__ node_b,
    const float* __restrict__ dg,         const int* __restrict__ batch, int n,
    const float* __restrict__ dgw,        const float* __restrict__ dgb,
    float* __restrict__ WVO, float* __restrict__ BVO,
    float* __restrict__ M1,  float* __restrict__ B2,
    __half* __restrict__ WFh, float* __restrict__ U, float* __restrict__ V,
    float* __restrict__ G)
{
    const int blk = blockIdx.x;
    const int t = threadIdx.x;
    __shared__ float r1[CC], r2[CC];

    if (blk < 512) {
        const int i = (blk < 256) ? blk : blk - 256;
        const float* Wo  = (blk < 256) ? out_proj_w : (fuse_w + CC);
        const int    lda = (blk < 256) ? CC : 2 * CC;
        const float* Wv  = (blk < 256) ? (in_proj_w + 2 * CC * CC) : l2w;
        const float* bv  = (blk < 256) ? (in_proj_b + 2 * CC) : l2b;
        const float* bo  = (blk < 256) ? out_proj_b : fuse_b;
        float* Wout = (blk < 256) ? WVO : M1;
        float* bout = (blk < 256) ? BVO : B2;

        r1[t] = Wo[(size_t)i * lda + t];
        __syncthreads();
        float s = 0.f;
        #pragma unroll 8
        for (int j = 0; j < CC; j++) s += r1[j] * Wv[j * CC + t];
        Wout[i * CC + t] = s;
        r2[t] = r1[t] * bv[t];
        __syncthreads();
        for (int o = 128; o > 0; o >>= 1) {
            if (t < o) r2[t] += r2[t + o];
            __syncthreads();
        }
        if (t == 0) bout[i] = r2[0] + bo[i];
    } else if (blk < 768) {
        const int i = blk - 512;
        const float fw = fuse_w[(size_t)i * 2 * CC + t];
        const __half hv = __float2half(node_w[t] * fw);
        WFh[i * CC + t] = hv;
        r1[t] = __half2float(hv);
        r2[t] = node_b[t] * fw;
        __syncthreads();
        for (int o = 128; o > 0; o >>= 1) {
            if (t < o) { r1[t] += r1[t + o]; r2[t] += r2[t + o]; }
            __syncthreads();
        }
        if (t == 0) { U[i] = r1[0]; V[i] = r2[0]; }
    } else {
        const int p = blk - 768;
        __shared__ int sb[2];
        if (t < 2) {
            int target = p + t;
            int lo = 0, hi = n;
            while (lo < hi) {
                int mid = (lo + hi) >> 1;
                if (batch[mid] < target) lo = mid + 1; else hi = mid;
            }
            sb[t] = lo;
        }
        __syncthreads();
        const int start = sb[0], end = sb[1];
        float s0 = 0.f, s1 = 0.f, s2 = 0.f, s3 = 0.f;
        int r = start;
        for (; r + 4 <= end; r += 4) {
            s0 += dg[(size_t)(r + 0) * CC + t];
            s1 += dg[(size_t)(r + 1) * CC + t];
            s2 += dg[(size_t)(r + 2) * CC + t];
            s3 += dg[(size_t)(r + 3) * CC + t];
        }
        for (; r < end; r++) s0 += dg[(size_t)r * CC + t];
        float s = (s0 + s1) + (s2 + s3);
        const int cnt = end - start;
        float mv = (cnt > 0) ? s / (float)cnt : 0.f;

        r1[t] = mv; __syncthreads();
        for (int o = 128; o > 0; o >>= 1) { if (t < o) r1[t] += r1[t + o]; __syncthreads(); }
        const float mu = r1[0] * (1.f / CC);
        __syncthreads();
        r1[t] = mv * mv; __syncthreads();
        for (int o = 128; o > 0; o >>= 1) { if (t < o) r1[t] += r1[t + o]; __syncthreads(); }
        const float var = r1[0] * (1.f / CC) - mu * mu;
        const float rstd = rsqrtf(var + 1e-5f);
        G[(size_t)p * CC + t] = (mv - mu) * rstd * dgw[t] + dgb[t];
    }
}

// ---------------- orig -> fp16 + exact LN stats (warp per row) ----------------
__global__ void prep_orig(const float4* __restrict__ in, __half* __restrict__ oh,
                          float* __restrict__ mu, float* __restrict__ rs, int rows)
{
    const int warp = blockIdx.x * 8 + (threadIdx.x >> 5);
    if (warp >= rows) return;
    const int lane = threadIdx.x & 31;
    const float4* rp = in + (size_t)warp * 64;
    const float4 a = rp[lane], b = rp[lane + 32];
    float s  = (a.x + a.y) + (a.z + a.w) + (b.x + b.y) + (b.z + b.w);
    float s2 = a.x*a.x + a.y*a.y + a.z*a.z + a.w*a.w
             + b.x*b.x + b.y*b.y + b.z*b.z + b.w*b.w;
    #pragma unroll
    for (int o = 16; o > 0; o >>= 1) {
        s  += __shfl_xor_sync(0xFFFFFFFFu, s,  o);
        s2 += __shfl_xor_sync(0xFFFFFFFFu, s2, o);
    }
    __half2 h0 = __floats2half2_rn(a.x, a.y), h1 = __floats2half2_rn(a.z, a.w);
    __half2 h2 = __floats2half2_rn(b.x, b.y), h3 = __floats2half2_rn(b.z, b.w);
    uint2* op = reinterpret_cast<uint2*>(oh + (size_t)warp * CC);
    op[lane]      = make_uint2(*(uint32_t*)&h0, *(uint32_t*)&h1);
    op[lane + 32] = make_uint2(*(uint32_t*)&h2, *(uint32_t*)&h3);
    if (lane == 0) {
        const float m = s * (1.f / CC);
        mu[warp] = m;
        rs[warp] = rsqrtf(s2 * (1.f / CC) - m * m + 1e-5f);
    }
}

// ---------------- warp-per-row LayerNorm (P rows) ----------------
__global__ void ln_rows(const float* __restrict__ in, const float* __restrict__ w,
                        const float* __restrict__ b, float* __restrict__ out, int rows)
{
    const int warp = blockIdx.x * (blockDim.x >> 5) + (threadIdx.x >> 5);
    if (warp >= rows) return;
    const int lane = threadIdx.x & 31;
    const float* rp = in + (size_t)warp * CC;
    float v[8];
    float s = 0.f, s2 = 0.f;
    #pragma unroll
    for (int i = 0; i < 8; i++) {
        v[i] = rp[lane + 32 * i];
        s  += v[i];
        s2 += v[i] * v[i];
    }
    #pragma unroll
    for (int o = 16; o > 0; o >>= 1) {
        s  += __shfl_xor_sync(0xFFFFFFFFu, s,  o);
        s2 += __shfl_xor_sync(0xFFFFFFFFu, s2, o);
    }
    const float mu  = s * (1.f / CC);
    const float var = s2 * (1.f / CC) - mu * mu;
    const float rstd = rsqrtf(var + 1e-5f);
    float* op = out + (size_t)warp * CC;
    #pragma unroll
    for (int i = 0; i < 8; i++) {
        const int c = lane + 32 * i;
        op[c] = (v[i] - mu) * rstd * w[c] + b[c];
    }
}

// ---------------- small tf32 wmma GEMM (unchanged, passing) ----------------
constexpr int BM = 128, BN = 64, BK = 32;
constexpr int LA = BK + 4;
constexpr int LC = BN + 4;

template<bool RELU, bool CAT>
__global__ __launch_bounds__(256)
void gemm_small(const float* __restrict__ A1, const float* __restrict__ B1, int ldb1,
                const float* __restrict__ A2, const float* __restrict__ B2x, int ldb2,
                float* __restrict__ C, const float* __restrict__ bias)
{
    __shared__ __align__(16) float smem[BM * LC];
    float* As = smem;
    float* Bs = smem + BM * LA;

    const int tid = threadIdx.x;
    const int warpId = tid >> 5;
    const int wm = warpId & 3;
    const int wn = warpId >> 2;
    const size_t gm = (size_t)blockIdx.y * BM;
    const int gn = blockIdx.x * BN;

    wmma::fragment<wmma::accumulator, 16, 16, 8, float> acc[2][2];
    #pragma unroll
    for (int i = 0; i < 2; i++)
        #pragma unroll
        for (int j = 0; j < 2; j++)
            wmma::fill_fragment(acc[i][j], 0.0f);

    const int lr = tid >> 3;
    const int lc = (tid & 7) << 2;
    const int KTOT = CAT ? 2 * CC : CC;

    for (int kt = 0; kt < KTOT; kt += BK) {
        const bool second = CAT && (kt >= CC);
        const float* A = second ? A2 : A1;
        const float* B = second ? B2x : B1;
        const int ldb = second ? ldb2 : ldb1;
        const int k0 = second ? kt - CC : kt;
        __syncthreads();
        #pragma unroll
        for (int p = 0; p < 4; p++) {
            const int r = lr + 32 * p;
            float4 v = *reinterpret_cast<const float4*>(A + (gm + r) * CC + k0 + lc);
            v.x = wmma::__float_to_tf32(v.x); v.y = wmma::__float_to_tf32(v.y);
            v.z = wmma::__float_to_tf32(v.z); v.w = wmma::__float_to_tf32(v.w);
            *reinterpret_cast<float4*>(&As[r * LA + lc]) = v;
        }
        #pragma unroll
        for (int p = 0; p < 2; p++) {
            const int r = lr + 32 * p;
            float4 v = *reinterpret_cast<const float4*>(B + (size_t)(gn + r) * ldb + k0 + lc);
            v.x = wmma::__float_to_tf32(v.x); v.y = wmma::__float_to_tf32(v.y);
            v.z = wmma::__float_to_tf32(v.z); v.w = wmma::__float_to_tf32(v.w);
            *reinterpret_cast<float4*>(&Bs[r * LA + lc]) = v;
        }
        __syncthreads();
        #pragma unroll
        for (int kk = 0; kk < BK; kk += 8) {
            wmma::fragment<wmma::matrix_a, 16, 16, 8, wmma::precision::tf32, wmma::row_major> af[2];
            wmma::fragment<wmma::matrix_b, 16, 16, 8, wmma::precision::tf32, wmma::col_major> bf[2];
            #pragma unroll
            for (int i = 0; i < 2; i++)
                wmma::load_matrix_sync(af[i], &As[(wm * 32 + 16 * i) * LA + kk], LA);
            #pragma unroll
            for (int j = 0; j < 2; j++)
                wmma::load_matrix_sync(bf[j], &Bs[(wn * 32 + 16 * j) * LA + kk], LA);
            #pragma unroll
            for (int i = 0; i < 2; i++)
                #pragma unroll
                for (int j = 0; j < 2; j++)
                    wmma::mma_sync(acc[i][j], af[i], bf[j], acc[i][j]);
        }
    }
    __syncthreads();
    #pragma unroll
    for (int i = 0; i < 2; i++)
        #pragma unroll
        for (int j = 0; j < 2; j++)
            wmma::store_matrix_sync(&smem[(wm * 32 + 16 * i) * LC + wn * 32 + 16 * j],
                                    acc[i][j], LC, wmma::mem_row_major);
    __syncthreads();

    const int ec = tid & 63;
    const int er = tid >> 6;
    #pragma unroll 4
    for (int r = er; r < BM; r += 4) {
        float c = smem[r * LC + ec] + bias[gn + ec];
        if (RELU) c = fmaxf(c, 0.0f);
        C[(gm + r) * CC + gn + ec] = c;
    }
}

// ================= BIG GEMM: pure fp16 cp.async streamer =================
// CTA 64x128, 8 warps (warp 32x32), BK=32, 3-stage cp.async pipeline.
// out[row,col] = relu( rs_r*(OH@W'.T) - rs_r*mu_r*u[col] + v[col] + g2[batch[row],col] )
//               + (oh[row,col]-mu_r)*rs_r*nw[col] + nb[col]
constexpr int GSTG   = 12288;               // A 4KB + B 8KB per stage
constexpr int EPILD  = 132;
constexpr int SM_BIG = 3 * GSTG;            // 36864 (epilogue 64*132*4=33792 reuses it)

__global__ __launch_bounds__(256)
void gemm_big_mma(const __half* __restrict__ OH,   // fp16 orig [N,256]
                  const __half* __restrict__ Bw,   // W' [256,256] fp16
                  const float* __restrict__ uvec, const float* __restrict__ vvec,
                  const int*   __restrict__ batch, const float* __restrict__ g2,
                  const float* __restrict__ nw, const float* __restrict__ nbv,
                  const float* __restrict__ mu_, const float* __restrict__ rs_,
                  float* __restrict__ out)
{
    extern __shared__ __align__(1024) char smc[];
    const uint32_t sbm = smem_u32(smc);
    const int tid  = threadIdx.x;
    const int wid  = tid >> 5;
    const int lane = tid & 31;
    const size_t gm = (size_t)blockIdx.y * 64;
    const int gn = blockIdx.x * 128;
    const int wm = wid & 1;        // 2 row blocks of 32
    const int wn = wid >> 1;       // 4 col blocks of 32

    float acc[2][4][4];
    #pragma unroll
    for (int i = 0; i < 2; i++)
        #pragma unroll
        for (int j = 0; j < 4; j++)
            #pragma unroll
            for (int e = 0; e < 4; e++) acc[i][j][e] = 0.f;

    // loaders: one 16B chunk per thread for A, two for B
    const int lrow = tid >> 2, lc16 = tid & 3;
    auto load_stage = [&](int s, int k0) {
        const uint32_t base = sbm + s * GSTG;
        cp_async16(base + hswz(lrow, lc16), OH + (gm + lrow) * CC + k0 + lc16 * 8);
        #pragma unroll
        for (int p = 0; p < 2; p++) {
            const int r = lrow + 64 * p;
            cp_async16(base + 4096 + hswz(r, lc16), Bw + (size_t)(gn + r) * CC + k0 + lc16 * 8);
        }
    };

    // ldsm address components (validated in R9)
    const int aR = lane & 15;
    const int aC = lane >> 4;
    const int bR = ((lane >> 4) << 3) + (lane & 7);
    const int bC = (lane >> 3) & 1;

    load_stage(0, 0);  CP_COMMIT();
    load_stage(1, 32); CP_COMMIT();

    #pragma unroll 1
    for (int kt = 0; kt < 8; kt++) {
        if (kt + 2 < 8) { CP_WAIT(1); } else { CP_WAIT(0); }
        __syncthreads();
        if (kt + 2 < 8) { load_stage((kt + 2) % 3, (kt + 2) * 32); CP_COMMIT(); }

        const int st = kt % 3;
        const uint32_t ab = sbm + st * GSTG;
        const uint32_t bb = ab + 4096;
        #pragma unroll
        for (int kk = 0; kk < 2; kk++) {
            uint32_t av[2][4];
            #pragma unroll
            for (int mi = 0; mi < 2; mi++)
                ldsm4(av[mi][0], av[mi][1], av[mi][2], av[mi][3],
                      ab + hswz(wm * 32 + mi * 16 + aR, kk * 2 + aC));
            uint32_t bv[2][4];
            #pragma unroll
            for (int nb = 0; nb < 2; nb++)
                ldsm4(bv[nb][0], bv[nb][1], bv[nb][2], bv[nb][3],
                      bb + hswz(wn * 32 + nb * 16 + bR, kk * 2 + bC));
            #pragma unroll
            for (int mi = 0; mi < 2; mi++)
                #pragma unroll
                for (int nb = 0; nb < 2; nb++) {
                    mma_f16(acc[mi][nb * 2 + 0], av[mi][0], av[mi][1], av[mi][2], av[mi][3],
                            bv[nb][0], bv[nb][1]);
                    mma_f16(acc[mi][nb * 2 + 1], av[mi][0], av[mi][1], av[mi][2], av[mi][3],
                            bv[nb][2], bv[nb][3]);
                }
        }
    }
    __syncthreads();   // mainloop smem reads done before epilogue overwrite

    // acc -> epilogue smem
    {
        float* ep = reinterpret_cast<float*>(smc);
        const int er0 = lane >> 2;
        const int ec0 = (lane & 3) * 2;
        #pragma unroll
        for (int mi = 0; mi < 2; mi++) {
            const int rb = wm * 32 + mi * 16 + er0;
            #pragma unroll
            for (int nj = 0; nj < 4; nj++) {
                const int cb = wn * 32 + nj * 8 + ec0;
                *reinterpret_cast<float2*>(ep + rb * EPILD + cb) =
                    make_float2(acc[mi][nj][0], acc[mi][nj][1]);
                *reinterpret_cast<float2*>(ep + (rb + 8) * EPILD + cb) =
                    make_float2(acc[mi][nj][2], acc[mi][nj][3]);
            }
        }
    }
    __syncthreads();

    // fused epilogue
    {
        const float* ep = reinterpret_cast<const float*>(smc);
        const int ec = tid & 127;
        const int col = gn + ec;
        const float un = uvec[col], vn = vvec[col];
        const float w_ = nw[col],  b_ = nbv[col];
        #pragma unroll 4
        for (int r = tid >> 7; r < 64; r += 2) {
            const size_t row = gm + r;
            const float m = mu_[row], rsv = rs_[row];
            float c = ep[r * EPILD + ec] * rsv - m * rsv * un + vn
                    + g2[(size_t)batch[row] * CC + col];
            c = fmaxf(c, 0.0f);
            const float o = __half2float(OH[row * CC + col]);   // L2-hot
            out[row * CC + col] = c + (o - m) * rsv * w_ + b_;
        }
    }
}

// ---------------- launcher ----------------
extern "C" void kernel_launch(void* const* d_in, const int* in_sizes, int n_in,
                              void* d_out, int out_size)
{
    const float* orig       = (const float*)d_in[0];
    const float* dgf        = (const float*)d_in[1];
    const float* node_w     = (const float*)d_in[2];
    const float* node_b     = (const float*)d_in[3];
    const float* dg_w       = (const float*)d_in[4];
    const float* dg_b       = (const float*)d_in[5];
    const float* in_proj_w  = (const float*)d_in[6];
    const float* in_proj_b  = (const float*)d_in[7];
    const float* out_proj_w = (const float*)d_in[8];
    const float* out_proj_b = (const float*)d_in[9];
    const float* ffn_w      = (const float*)d_in[10];
    const float* ffn_b      = (const float*)d_in[11];
    const float* l1w        = (const float*)d_in[12];
    const float* l1b        = (const float*)d_in[13];
    const float* l2w        = (const float*)d_in[14];
    const float* l2b        = (const float*)d_in[15];
    const float* fuse_w     = (const float*)d_in[16];
    const float* fuse_b     = (const float*)d_in[17];
    const int*   batch      = (const int*)d_in[18];
    const int n = in_sizes[0] / CC;   // 262144

    float *G, *ATT, *Y, *H, *G2, *WVO, *BVO, *M1, *B2, *U, *V, *MU, *RS;
    __half *WFh, *OH;
    cudaGetSymbolAddress((void**)&G,   g_G);
    cudaGetSymbolAddress((void**)&ATT, g_ATT);
    cudaGetSymbolAddress((void**)&Y,   g_Y);
    cudaGetSymbolAddress((void**)&H,   g_H);
    cudaGetSymbolAddress((void**)&G2,  g_G2);
    cudaGetSymbolAddress((void**)&WVO, g_WVO);
    cudaGetSymbolAddress((void**)&BVO, g_BVO);
    cudaGetSymbolAddress((void**)&M1,  g_M1);
    cudaGetSymbolAddress((void**)&B2,  g_B2);
    cudaGetSymbolAddress((void**)&WFh, g_WFh);
    cudaGetSymbolAddress((void**)&U,   g_U);
    cudaGetSymbolAddress((void**)&V,   g_V);
    cudaGetSymbolAddress((void**)&OH,  g_OH);
    cudaGetSymbolAddress((void**)&MU,  g_MU);
    cudaGetSymbolAddress((void**)&RS,  g_RS);

    cudaFuncSetAttribute(gemm_big_mma, cudaFuncAttributeMaxDynamicSharedMemorySize, SM_BIG);

    const dim3 sg(CC / BN, PP / BM);   // (4, 32)

    // 0: precomputes + segment-mean/LN
    fused_pre_seg<<<768 + PP, 256>>>(
        out_proj_w, in_proj_w, in_proj_b, out_proj_b,
        fuse_w, l2w, l2b, fuse_b, node_w, node_b,
        dgf, batch, n, dg_w, dg_b,
        WVO, BVO, M1, B2, WFh, U, V, G);
    // 1: orig -> fp16 + LN stats
    prep_orig<<<n / 8, 256>>>((const float4*)orig, OH, MU, RS, n);
    // 2: ATT = G @ WVO.T + BVO
    gemm_small<false, false><<<sg, 256>>>(G, WVO, CC, nullptr, nullptr, 0, ATT, BVO);
    // 3: Y = LN(ATT)
    ln_rows<<<PP / 8, 256>>>(ATT, ffn_w, ffn_b, Y, PP);
    // 4: H = relu(Y @ l1w.T + l1b)
    gemm_small<true, false><<<sg, 256>>>(Y, l1w, CC, nullptr, nullptr, 0, H, l1b);
    // 5: G2 = H @ M1.T + ATT @ Wf2.T + B2
    gemm_small<false, true><<<sg, 256>>>(H, M1, CC, ATT, fuse_w + CC, 2 * CC, G2, B2);
    // 6: big fused node GEMM (pure fp16 pipeline)
    gemm_big_mma<<<dim3(2, n / 64), 256, SM_BIG>>>(
        OH, WFh, U, V, batch, G2, node_w, node_b, MU, RS, (float*)d_out);
}

// round 11
// speedup vs baseline: 1.0981x; 1.0981x over previous
#include <cuda_runtime.h>
#include <cuda_fp16.h>
#include <cuda_bf16.h>
#include <mma.h>
#include <cstdint>
#include <cstddef>

using namespace nvcuda;

#define CC 256
#define PP 4096
#define NN 262144

// ---------------- scratch (device globals: no allocation allowed) ----------------
static __device__ float  g_G   [PP * CC];
static __device__ float  g_ATT [PP * CC];
static __device__ float  g_Y   [PP * CC];
static __device__ float  g_H   [PP * CC];
static __device__ float  g_G2  [PP * CC];
static __device__ float  g_WVO [CC * CC];
static __device__ float  g_BVO [CC];
static __device__ float  g_M1  [CC * CC];
static __device__ float  g_B2  [CC];
static __device__ __half g_WFh [CC * CC];
static __device__ float  g_U   [CC];
static __device__ float  g_V   [CC];
static __device__ __half g_OH  [(size_t)NN * CC];
static __device__ float  g_MU  [NN];
static __device__ float  g_RS  [NN];

// ---------------- helpers ----------------
__device__ __forceinline__ uint32_t smem_u32(const void* p) {
    uint32_t a;
    asm("{ .reg .u64 t; cvta.to.shared.u64 t, %1; cvt.u32.u64 %0, t; }" : "=r"(a) : "l"(p));
    return a;
}
__device__ __forceinline__ void cp_async16(uint32_t smem, const void* gmem) {
    asm volatile("cp.async.cg.shared.global [%0], [%1], 16;\n" :: "r"(smem), "l"(gmem));
}
#define CP_COMMIT() asm volatile("cp.async.commit_group;\n" ::: "memory")
#define CP_WAIT(n)  asm volatile("cp.async.wait_group %0;\n" :: "n"(n) : "memory")

__device__ __forceinline__ void ldsm4(uint32_t& r0, uint32_t& r1, uint32_t& r2, uint32_t& r3,
                                      uint32_t addr) {
    asm volatile("ldmatrix.sync.aligned.m8n8.x4.shared.b16 {%0,%1,%2,%3}, [%4];"
                 : "=r"(r0), "=r"(r1), "=r"(r2), "=r"(r3) : "r"(addr));
}
__device__ __forceinline__ void mma_f16(float* d, uint32_t a0, uint32_t a1, uint32_t a2,
                                        uint32_t a3, uint32_t b0, uint32_t b1) {
    asm volatile(
        "mma.sync.aligned.m16n8k16.row.col.f32.f16.f16.f32 "
        "{%0,%1,%2,%3}, {%4,%5,%6,%7}, {%8,%9}, {%0,%1,%2,%3};"
        : "+f"(d[0]), "+f"(d[1]), "+f"(d[2]), "+f"(d[3])
        : "r"(a0), "r"(a1), "r"(a2), "r"(a3), "r"(b0), "r"(b1));
}

// 16B-chunk swizzle within a 64B row (validated R9/R10)
__device__ __forceinline__ uint32_t hswz(int row, int c16) {
    return (uint32_t)(row * 64 + (c16 ^ ((row >> 1) & 3)) * 16);
}

// ================ launch 0: precomputes + segment-mean + orig prep ================
// [0,256): WVO/BVO  [256,512): M1/B2  [512,768): WFh/U/V  [768,768+P): seg_mean
// [768+P, 768+P+N/8): orig -> fp16 + LN stats (8 rows/block)
__global__ void fused_pre_seg(
    const float* __restrict__ out_proj_w, const float* __restrict__ in_proj_w,
    const float* __restrict__ in_proj_b,  const float* __restrict__ out_proj_b,
    const float* __restrict__ fuse_w,     const float* __restrict__ l2w,
    const float* __restrict__ l2b,        const float* __restrict__ fuse_b,
    const float* __restrict__ node_w,     const float* __restrict__ node_b,
    const float* __restrict__ dg,         const int* __restrict__ batch, int n,
    const float* __restrict__ dgw,        const float* __restrict__ dgb,
    const float4* __restrict__ orig4,
    float* __restrict__ WVO, float* __restrict__ BVO,
    float* __restrict__ M1,  float* __restrict__ B2,
    __half* __restrict__ WFh, float* __restrict__ U, float* __restrict__ V,
    float* __restrict__ G,
    __half* __restrict__ OH, float* __restrict__ MU, float* __restrict__ RS)
{
    const int blk = blockIdx.x;
    const int t = threadIdx.x;
    __shared__ float r1[CC], r2[CC];

    if (blk < 512) {
        const int i = (blk < 256) ? blk : blk - 256;
        const float* Wo  = (blk < 256) ? out_proj_w : (fuse_w + CC);
        const int    lda = (blk < 256) ? CC : 2 * CC;
        const float* Wv  = (blk < 256) ? (in_proj_w + 2 * CC * CC) : l2w;
        const float* bv  = (blk < 256) ? (in_proj_b + 2 * CC) : l2b;
        const float* bo  = (blk < 256) ? out_proj_b : fuse_b;
        float* Wout = (blk < 256) ? WVO : M1;
        float* bout = (blk < 256) ? BVO : B2;

        r1[t] = Wo[(size_t)i * lda + t];
        __syncthreads();
        float s = 0.f;
        #pragma unroll 8
        for (int j = 0; j < CC; j++) s += r1[j] * Wv[j * CC + t];
        Wout[i * CC + t] = s;
        r2[t] = r1[t] * bv[t];
        __syncthreads();
        for (int o = 128; o > 0; o >>= 1) {
            if (t < o) r2[t] += r2[t + o];
            __syncthreads();
        }
        if (t == 0) bout[i] = r2[0] + bo[i];
    } else if (blk < 768) {
        const int i = blk - 512;
        const float fw = fuse_w[(size_t)i * 2 * CC + t];
        const __half hv = __float2half(node_w[t] * fw);
        WFh[i * CC + t] = hv;
        r1[t] = __half2float(hv);
        r2[t] = node_b[t] * fw;
        __syncthreads();
        for (int o = 128; o > 0; o >>= 1) {
            if (t < o) { r1[t] += r1[t + o]; r2[t] += r2[t + o]; }
            __syncthreads();
        }
        if (t == 0) { U[i] = r1[0]; V[i] = r2[0]; }
    } else if (blk < 768 + PP) {
        const int p = blk - 768;
        __shared__ int sb[2];
        if (t < 2) {
            int target = p + t;
            int lo = 0, hi = n;
            while (lo < hi) {
                int mid = (lo + hi) >> 1;
                if (batch[mid] < target) lo = mid + 1; else hi = mid;
            }
            sb[t] = lo;
        }
        __syncthreads();
        const int start = sb[0], end = sb[1];
        float s0 = 0.f, s1 = 0.f, s2 = 0.f, s3 = 0.f;
        int r = start;
        for (; r + 4 <= end; r += 4) {
            s0 += dg[(size_t)(r + 0) * CC + t];
            s1 += dg[(size_t)(r + 1) * CC + t];
            s2 += dg[(size_t)(r + 2) * CC + t];
            s3 += dg[(size_t)(r + 3) * CC + t];
        }
        for (; r < end; r++) s0 += dg[(size_t)r * CC + t];
        float s = (s0 + s1) + (s2 + s3);
        const int cnt = end - start;
        float mv = (cnt > 0) ? s / (float)cnt : 0.f;

        r1[t] = mv; __syncthreads();
        for (int o = 128; o > 0; o >>= 1) { if (t < o) r1[t] += r1[t + o]; __syncthreads(); }
        const float mu = r1[0] * (1.f / CC);
        __syncthreads();
        r1[t] = mv * mv; __syncthreads();
        for (int o = 128; o > 0; o >>= 1) { if (t < o) r1[t] += r1[t + o]; __syncthreads(); }
        const float var = r1[0] * (1.f / CC) - mu * mu;
        const float rstd = rsqrtf(var + 1e-5f);
        G[(size_t)p * CC + t] = (mv - mu) * rstd * dgw[t] + dgb[t];
    } else {
        // orig -> fp16 + exact LN stats, warp per row
        const int row = (blk - 768 - PP) * 8 + (t >> 5);
        const int lane = t & 31;
        const float4* rp = orig4 + (size_t)row * 64;
        const float4 a = rp[lane], b = rp[lane + 32];
        float s  = (a.x + a.y) + (a.z + a.w) + (b.x + b.y) + (b.z + b.w);
        float s2 = a.x*a.x + a.y*a.y + a.z*a.z + a.w*a.w
                 + b.x*b.x + b.y*b.y + b.z*b.z + b.w*b.w;
        #pragma unroll
        for (int o = 16; o > 0; o >>= 1) {
            s  += __shfl_xor_sync(0xFFFFFFFFu, s,  o);
            s2 += __shfl_xor_sync(0xFFFFFFFFu, s2, o);
        }
        __half2 h0 = __floats2half2_rn(a.x, a.y), h1 = __floats2half2_rn(a.z, a.w);
        __half2 h2 = __floats2half2_rn(b.x, b.y), h3 = __floats2half2_rn(b.z, b.w);
        uint2* op = reinterpret_cast<uint2*>(OH + (size_t)row * CC);
        op[lane]      = make_uint2(*(uint32_t*)&h0, *(uint32_t*)&h1);
        op[lane + 32] = make_uint2(*(uint32_t*)&h2, *(uint32_t*)&h3);
        if (lane == 0) {
            const float m = s * (1.f / CC);
            MU[row] = m;
            RS[row] = rsqrtf(s2 * (1.f / CC) - m * m + 1e-5f);
        }
    }
}

// ---------------- warp-per-row LayerNorm (P rows) ----------------
__global__ void ln_rows(const float* __restrict__ in, const float* __restrict__ w,
                        const float* __restrict__ b, float* __restrict__ out, int rows)
{
    const int warp = blockIdx.x * (blockDim.x >> 5) + (threadIdx.x >> 5);
    if (warp >= rows) return;
    const int lane = threadIdx.x & 31;
    const float* rp = in + (size_t)warp * CC;
    float v[8];
    float s = 0.f, s2 = 0.f;
    #pragma unroll
    for (int i = 0; i < 8; i++) {
        v[i] = rp[lane + 32 * i];
        s  += v[i];
        s2 += v[i] * v[i];
    }
    #pragma unroll
    for (int o = 16; o > 0; o >>= 1) {
        s  += __shfl_xor_sync(0xFFFFFFFFu, s,  o);
        s2 += __shfl_xor_sync(0xFFFFFFFFu, s2, o);
    }
    const float mu  = s * (1.f / CC);
    const float var = s2 * (1.f / CC) - mu * mu;
    const float rstd = rsqrtf(var + 1e-5f);
    float* op = out + (size_t)warp * CC;
    #pragma unroll
    for (int i = 0; i < 8; i++) {
        const int c = lane + 32 * i;
        op[c] = (v[i] - mu) * rstd * w[c] + b[c];
    }
}

// ---------------- small tf32 wmma GEMM (unchanged, passing) ----------------
constexpr int BM = 128, BN = 64, BK = 32;
constexpr int LA = BK + 4;
constexpr int LC = BN + 4;

template<bool RELU, bool CAT>
__global__ __launch_bounds__(256)
void gemm_small(const float* __restrict__ A1, const float* __restrict__ B1, int ldb1,
                const float* __restrict__ A2, const float* __restrict__ B2x, int ldb2,
                float* __restrict__ C, const float* __restrict__ bias)
{
    __shared__ __align__(16) float smem[BM * LC];
    float* As = smem;
    float* Bs = smem + BM * LA;

    const int tid = threadIdx.x;
    const int warpId = tid >> 5;
    const int wm = warpId & 3;
    const int wn = warpId >> 2;
    const size_t gm = (size_t)blockIdx.y * BM;
    const int gn = blockIdx.x * BN;

    wmma::fragment<wmma::accumulator, 16, 16, 8, float> acc[2][2];
    #pragma unroll
    for (int i = 0; i < 2; i++)
        #pragma unroll
        for (int j = 0; j < 2; j++)
            wmma::fill_fragment(acc[i][j], 0.0f);

    const int lr = tid >> 3;
    const int lc = (tid & 7) << 2;
    const int KTOT = CAT ? 2 * CC : CC;

    for (int kt = 0; kt < KTOT; kt += BK) {
        const bool second = CAT && (kt >= CC);
        const float* A = second ? A2 : A1;
        const float* B = second ? B2x : B1;
        const int ldb = second ? ldb2 : ldb1;
        const int k0 = second ? kt - CC : kt;
        __syncthreads();
        #pragma unroll
        for (int p = 0; p < 4; p++) {
            const int r = lr + 32 * p;
            float4 v = *reinterpret_cast<const float4*>(A + (gm + r) * CC + k0 + lc);
            v.x = wmma::__float_to_tf32(v.x); v.y = wmma::__float_to_tf32(v.y);
            v.z = wmma::__float_to_tf32(v.z); v.w = wmma::__float_to_tf32(v.w);
            *reinterpret_cast<float4*>(&As[r * LA + lc]) = v;
        }
        #pragma unroll
        for (int p = 0; p < 2; p++) {
            const int r = lr + 32 * p;
            float4 v = *reinterpret_cast<const float4*>(B + (size_t)(gn + r) * ldb + k0 + lc);
            v.x = wmma::__float_to_tf32(v.x); v.y = wmma::__float_to_tf32(v.y);
            v.z = wmma::__float_to_tf32(v.z); v.w = wmma::__float_to_tf32(v.w);
            *reinterpret_cast<float4*>(&Bs[r * LA + lc]) = v;
        }
        __syncthreads();
        #pragma unroll
        for (int kk = 0; kk < BK; kk += 8) {
            wmma::fragment<wmma::matrix_a, 16, 16, 8, wmma::precision::tf32, wmma::row_major> af[2];
            wmma::fragment<wmma::matrix_b, 16, 16, 8, wmma::precision::tf32, wmma::col_major> bf[2];
            #pragma unroll
            for (int i = 0; i < 2; i++)
                wmma::load_matrix_sync(af[i], &As[(wm * 32 + 16 * i) * LA + kk], LA);
            #pragma unroll
            for (int j = 0; j < 2; j++)
                wmma::load_matrix_sync(bf[j], &Bs[(wn * 32 + 16 * j) * LA + kk], LA);
            #pragma unroll
            for (int i = 0; i < 2; i++)
                #pragma unroll
                for (int j = 0; j < 2; j++)
                    wmma::mma_sync(acc[i][j], af[i], bf[j], acc[i][j]);
        }
    }
    __syncthreads();
    #pragma unroll
    for (int i = 0; i < 2; i++)
        #pragma unroll
        for (int j = 0; j < 2; j++)
            wmma::store_matrix_sync(&smem[(wm * 32 + 16 * i) * LC + wn * 32 + 16 * j],
                                    acc[i][j], LC, wmma::mem_row_major);
    __syncthreads();

    const int ec = tid & 63;
    const int er = tid >> 6;
    #pragma unroll 4
    for (int r = er; r < BM; r += 4) {
        float c = smem[r * LC + ec] + bias[gn + ec];
        if (RELU) c = fmaxf(c, 0.0f);
        C[(gm + r) * CC + gn + ec] = c;
    }
}

// ================= BIG GEMM: full-width 128x256, all-resident smem =================
// 512 threads (16 warps, warp 32x64). A (128x256 fp16) + B (256x256 fp16) fully resident.
// All 8 K-chunk loads issued up-front; loop = wait/bar/ldsm/mma. Direct-STG epilogue
// with residual read from resident A smem.
constexpr int SMB_A   = 0;                       // 8 slots x 8192
constexpr int SMB_B   = 65536;                   // 8 slots x 16384
constexpr int SMB_U   = 196608;                  // 256 f
constexpr int SMB_V   = SMB_U  + 1024;
constexpr int SMB_NW  = SMB_V  + 1024;
constexpr int SMB_NB  = SMB_NW + 1024;
constexpr int SMB_MU  = SMB_NB + 1024;           // 128 f
constexpr int SMB_RS  = SMB_MU + 512;
constexpr int SMB_BT  = SMB_RS + 512;            // 128 i
constexpr int SM_BIG  = SMB_BT + 512;            // 202240 B

__global__ __launch_bounds__(512)
void gemm_big_mma(const __half* __restrict__ OH,   // fp16 orig [N,256]
                  const __half* __restrict__ Bw,   // W' [256,256] fp16
                  const float* __restrict__ uvec, const float* __restrict__ vvec,
                  const int*   __restrict__ batch, const float* __restrict__ g2,
                  const float* __restrict__ nw, const float* __restrict__ nbv,
                  const float* __restrict__ mu_, const float* __restrict__ rs_,
                  float* __restrict__ out)
{
    extern __shared__ __align__(1024) char smc[];
    const uint32_t sbm = smem_u32(smc);
    const int tid  = threadIdx.x;
    const int wid  = tid >> 5;
    const int lane = tid & 31;
    const size_t gm = (size_t)blockIdx.x * 128;
    const int wm = wid & 3;        // 4 row blocks of 32
    const int wn = wid >> 2;       // 4 col blocks of 64

    // stage params into smem (plain LDG/STS; covered by mainloop barriers)
    if (tid < 256) {
        *reinterpret_cast<float*>(smc + SMB_U  + tid * 4) = uvec[tid];
        *reinterpret_cast<float*>(smc + SMB_V  + tid * 4) = vvec[tid];
        *reinterpret_cast<float*>(smc + SMB_NW + tid * 4) = nw[tid];
        *reinterpret_cast<float*>(smc + SMB_NB + tid * 4) = nbv[tid];
    } else if (tid < 384) {
        const int r = tid - 256;
        *reinterpret_cast<float*>(smc + SMB_MU + r * 4) = mu_[gm + r];
        *reinterpret_cast<float*>(smc + SMB_RS + r * 4) = rs_[gm + r];
        *reinterpret_cast<int*>  (smc + SMB_BT + r * 4) = batch[gm + r];
    }

    // issue ALL 8 chunk loads up-front (slots persistent, one group per chunk)
    {
        const int lrow = tid >> 2, lc16 = tid & 3;
        #pragma unroll
        for (int c = 0; c < 8; c++) {
            const uint32_t a0 = sbm + SMB_A + c * 8192;
            const uint32_t b0 = sbm + SMB_B + c * 16384;
            cp_async16(a0 + hswz(lrow, lc16), OH + (gm + lrow) * CC + c * 32 + lc16 * 8);
            cp_async16(b0 + hswz(lrow, lc16), Bw + (size_t)lrow * CC + c * 32 + lc16 * 8);
            cp_async16(b0 + hswz(lrow + 128, lc16),
                       Bw + (size_t)(lrow + 128) * CC + c * 32 + lc16 * 8);
            CP_COMMIT();
        }
    }

    float acc[2][8][4];
    #pragma unroll
    for (int i = 0; i < 2; i++)
        #pragma unroll
        for (int j = 0; j < 8; j++)
            #pragma unroll
            for (int e = 0; e < 4; e++) acc[i][j][e] = 0.f;

    // ldsm lane-address components (validated R9/R10)
    const int aR = lane & 15;
    const int aC = lane >> 4;
    const int bR = ((lane >> 4) << 3) + (lane & 7);
    const int bC = (lane >> 3) & 1;

    #pragma unroll 1
    for (int kt = 0; kt < 8; kt++) {
        switch (kt) {
            case 0: CP_WAIT(7); break;
            case 1: CP_WAIT(6); break;
            case 2: CP_WAIT(5); break;
            case 3: CP_WAIT(4); break;
            case 4: CP_WAIT(3); break;
            case 5: CP_WAIT(2); break;
            case 6: CP_WAIT(1); break;
            default: CP_WAIT(0); break;
        }
        __syncthreads();

        const uint32_t ab = sbm + SMB_A + kt * 8192;
        const uint32_t bb = sbm + SMB_B + kt * 16384;
        #pragma unroll
        for (int kk = 0; kk < 2; kk++) {
            uint32_t av[2][4];
            #pragma unroll
            for (int mi = 0; mi < 2; mi++)
                ldsm4(av[mi][0], av[mi][1], av[mi][2], av[mi][3],
                      ab + hswz(wm * 32 + mi * 16 + aR, kk * 2 + aC));
            uint32_t bv[4][4];
            #pragma unroll
            for (int nb = 0; nb < 4; nb++)
                ldsm4(bv[nb][0], bv[nb][1], bv[nb][2], bv[nb][3],
                      bb + hswz(wn * 64 + nb * 16 + bR, kk * 2 + bC));
            #pragma unroll
            for (int mi = 0; mi < 2; mi++)
                #pragma unroll
                for (int nb = 0; nb < 4; nb++) {
                    mma_f16(acc[mi][nb * 2 + 0], av[mi][0], av[mi][1], av[mi][2], av[mi][3],
                            bv[nb][0], bv[nb][1]);
                    mma_f16(acc[mi][nb * 2 + 1], av[mi][0], av[mi][1], av[mi][2], av[mi][3],
                            bv[nb][2], bv[nb][3]);
                }
        }
    }

    // ---- direct-STG fused epilogue (residual from resident A smem) ----
    {
        const float* su  = reinterpret_cast<const float*>(smc + SMB_U);
        const float* sv  = reinterpret_cast<const float*>(smc + SMB_V);
        const float* sw  = reinterpret_cast<const float*>(smc + SMB_NW);
        const float* sbb = reinterpret_cast<const float*>(smc + SMB_NB);
        const float* smu = reinterpret_cast<const float*>(smc + SMB_MU);
        const float* srs = reinterpret_cast<const float*>(smc + SMB_RS);
        const int*   sbt = reinterpret_cast<const int*>  (smc + SMB_BT);
        #pragma unroll
        for (int mi = 0; mi < 2; mi++) {
            #pragma unroll
            for (int rh = 0; rh < 2; rh++) {
                const int r = wm * 32 + mi * 16 + (lane >> 2) + rh * 8;
                const size_t row = gm + r;
                const float m = smu[r], rsv = srs[r];
                const float mrs = m * rsv;
                const float* g2row = g2 + (size_t)sbt[r] * CC;
                #pragma unroll
                for (int nj = 0; nj < 8; nj++) {
                    const int c = wn * 64 + nj * 8 + (lane & 3) * 2;
                    const float2 g = *reinterpret_cast<const float2*>(g2row + c);
                    float v0 = acc[mi][nj][rh * 2 + 0] * rsv - mrs * su[c]     + sv[c]     + g.x;
                    float v1 = acc[mi][nj][rh * 2 + 1] * rsv - mrs * su[c + 1] + sv[c + 1] + g.y;
                    v0 = fmaxf(v0, 0.f);
                    v1 = fmaxf(v1, 0.f);
                    // residual: orig (fp16) from resident A smem slot (c>>5), 16B-chunk (c&31)>>3
                    const __half2 oh2 = *reinterpret_cast<const __half2*>(
                        smc + SMB_A + (c >> 5) * 8192 + hswz(r, (c & 31) >> 3) + (c & 7) * 2);
                    v0 += (__half2float(oh2.x) - m) * rsv * sw[c]     + sbb[c];
                    v1 += (__half2float(oh2.y) - m) * rsv * sw[c + 1] + sbb[c + 1];
                    *reinterpret_cast<float2*>(out + row * CC + c) = make_float2(v0, v1);
                }
            }
        }
    }
}

// ---------------- launcher ----------------
extern "C" void kernel_launch(void* const* d_in, const int* in_sizes, int n_in,
                              void* d_out, int out_size)
{
    const float* orig       = (const float*)d_in[0];
    const float* dgf        = (const float*)d_in[1];
    const float* node_w     = (const float*)d_in[2];
    const float* node_b     = (const float*)d_in[3];
    const float* dg_w       = (const float*)d_in[4];
    const float* dg_b       = (const float*)d_in[5];
    const float* in_proj_w  = (const float*)d_in[6];
    const float* in_proj_b  = (const float*)d_in[7];
    const float* out_proj_w = (const float*)d_in[8];
    const float* out_proj_b = (const float*)d_in[9];
    const float* ffn_w      = (const float*)d_in[10];
    const float* ffn_b      = (const float*)d_in[11];
    const float* l1w        = (const float*)d_in[12];
    const float* l1b        = (const float*)d_in[13];
    const float* l2w        = (const float*)d_in[14];
    const float* l2b        = (const float*)d_in[15];
    const float* fuse_w     = (const float*)d_in[16];
    const float* fuse_b     = (const float*)d_in[17];
    const int*   batch      = (const int*)d_in[18];
    const int n = in_sizes[0] / CC;   // 262144

    float *G, *ATT, *Y, *H, *G2, *WVO, *BVO, *M1, *B2, *U, *V, *MU, *RS;
    __half *WFh, *OH;
    cudaGetSymbolAddress((void**)&G,   g_G);
    cudaGetSymbolAddress((void**)&ATT, g_ATT);
    cudaGetSymbolAddress((void**)&Y,   g_Y);
    cudaGetSymbolAddress((void**)&H,   g_H);
    cudaGetSymbolAddress((void**)&G2,  g_G2);
    cudaGetSymbolAddress((void**)&WVO, g_WVO);
    cudaGetSymbolAddress((void**)&BVO, g_BVO);
    cudaGetSymbolAddress((void**)&M1,  g_M1);
    cudaGetSymbolAddress((void**)&B2,  g_B2);
    cudaGetSymbolAddress((void**)&WFh, g_WFh);
    cudaGetSymbolAddress((void**)&U,   g_U);
    cudaGetSymbolAddress((void**)&V,   g_V);
    cudaGetSymbolAddress((void**)&OH,  g_OH);
    cudaGetSymbolAddress((void**)&MU,  g_MU);
    cudaGetSymbolAddress((void**)&RS,  g_RS);

    cudaFuncSetAttribute(gemm_big_mma, cudaFuncAttributeMaxDynamicSharedMemorySize, SM_BIG);

    const dim3 sg(CC / BN, PP / BM);   // (4, 32)

    // 0: precomputes + segment-mean/LN + orig->fp16 prep (one kernel)
    fused_pre_seg<<<768 + PP + n / 8, 256>>>(
        out_proj_w, in_proj_w, in_proj_b, out_proj_b,
        fuse_w, l2w, l2b, fuse_b, node_w, node_b,
        dgf, batch, n, dg_w, dg_b, (const float4*)orig,
        WVO, BVO, M1, B2, WFh, U, V, G, OH, MU, RS);
    // 1: ATT = G @ WVO.T + BVO
    gemm_small<false, false><<<sg, 256>>>(G, WVO, CC, nullptr, nullptr, 0, ATT, BVO);
    // 2: Y = LN(ATT)
    ln_rows<<<PP / 8, 256>>>(ATT, ffn_w, ffn_b, Y, PP);
    // 3: H = relu(Y @ l1w.T + l1b)
    gemm_small<true, false><<<sg, 256>>>(Y, l1w, CC, nullptr, nullptr, 0, H, l1b);
    // 4: G2 = H @ M1.T + ATT @ Wf2.T + B2
    gemm_small<false, true><<<sg, 256>>>(H, M1, CC, ATT, fuse_w + CC, 2 * CC, G2, B2);
    // 5: big fused node GEMM (full-width, all-resident smem)
    gemm_big_mma<<<n / 128, 512, SM_BIG>>>(
        OH, WFh, U, V, batch, G2, node_w, node_b, MU, RS, (float*)d_out);
}

// round 17
// speedup vs baseline: 1.2593x; 1.1467x over previous
#include <cuda_runtime.h>
#include <cuda_fp16.h>
#include <cuda_bf16.h>
#include <mma.h>
#include <cstdint>
#include <cstddef>

using namespace nvcuda;

#define CC 256
#define PP 4096
#define NN 262144

// ---------------- scratch (device globals: no allocation allowed) ----------------
static __device__ float  g_G   [PP * CC];
static __device__ float  g_ATT [PP * CC];
static __device__ float  g_Y   [PP * CC];
static __device__ float  g_H   [PP * CC];
static __device__ float  g_G2  [PP * CC];
static __device__ float  g_WVO [CC * CC];
static __device__ float  g_BVO [CC];
static __device__ float  g_M1  [CC * CC];
static __device__ float  g_B2  [CC];
static __device__ __half g_WFh [CC * CC];
static __device__ float  g_U   [CC];
static __device__ float  g_V   [CC];
static __device__ __half g_OH  [(size_t)NN * CC];
static __device__ float  g_MU  [NN];
static __device__ float  g_RS  [NN];

// ---------------- helpers ----------------
__device__ __forceinline__ uint32_t smem_u32(const void* p) {
    uint32_t a;
    asm("{ .reg .u64 t; cvta.to.shared.u64 t, %1; cvt.u32.u64 %0, t; }" : "=r"(a) : "l"(p));
    return a;
}
__device__ __forceinline__ void cp_async16(uint32_t smem, const void* gmem) {
    asm volatile("cp.async.cg.shared.global [%0], [%1], 16;\n" :: "r"(smem), "l"(gmem));
}
#define CP_COMMIT() asm volatile("cp.async.commit_group;\n" ::: "memory")
#define CP_WAIT(n)  asm volatile("cp.async.wait_group %0;\n" :: "n"(n) : "memory")

__device__ __forceinline__ void ldsm4(uint32_t& r0, uint32_t& r1, uint32_t& r2, uint32_t& r3,
                                      uint32_t addr) {
    asm volatile("ldmatrix.sync.aligned.m8n8.x4.shared.b16 {%0,%1,%2,%3}, [%4];"
                 : "=r"(r0), "=r"(r1), "=r"(r2), "=r"(r3) : "r"(addr));
}
__device__ __forceinline__ void mma_f16(float* d, uint32_t a0, uint32_t a1, uint32_t a2,
                                        uint32_t a3, uint32_t b0, uint32_t b1) {
    asm volatile(
        "mma.sync.aligned.m16n8k16.row.col.f32.f16.f16.f32 "
        "{%0,%1,%2,%3}, {%4,%5,%6,%7}, {%8,%9}, {%0,%1,%2,%3};"
        : "+f"(d[0]), "+f"(d[1]), "+f"(d[2]), "+f"(d[3])
        : "r"(a0), "r"(a1), "r"(a2), "r"(a3), "r"(b0), "r"(b1));
}

// 16B-chunk swizzle within a 64B row (validated R9-R11)
__device__ __forceinline__ uint32_t hswz(int row, int c16) {
    return (uint32_t)(row * 64 + (c16 ^ ((row >> 1) & 3)) * 16);
}

// ================ launch 0: precomputes + segment-mean + orig prep ================
__global__ void fused_pre_seg(
    const float* __restrict__ out_proj_w, const float* __restrict__ in_proj_w,
    const float* __restrict__ in_proj_b,  const float* __restrict__ out_proj_b,
    const float* __restrict__ fuse_w,     const float* __restrict__ l2w,
    const float* __restrict__ l2b,        const float* __restrict__ fuse_b,
    const float* __restrict__ node_w,     const float* __restrict__ node_b,
    const float* __restrict__ dg,         const int* __restrict__ batch, int n,
    const float* __restrict__ dgw,        const float* __restrict__ dgb,
    const float4* __restrict__ orig4,
    float* __restrict__ WVO, float* __restrict__ BVO,
    float* __restrict__ M1,  float* __restrict__ B2,
    __half* __restrict__ WFh, float* __restrict__ U, float* __restrict__ V,
    float* __restrict__ G,
    __half* __restrict__ OH, float* __restrict__ MU, float* __restrict__ RS)
{
    const int blk = blockIdx.x;
    const int t = threadIdx.x;
    __shared__ float r1[CC], r2[CC];

    if (blk < 512) {
        const int i = (blk < 256) ? blk : blk - 256;
        const float* Wo  = (blk < 256) ? out_proj_w : (fuse_w + CC);
        const int    lda = (blk < 256) ? CC : 2 * CC;
        const float* Wv  = (blk < 256) ? (in_proj_w + 2 * CC * CC) : l2w;
        const float* bv  = (blk < 256) ? (in_proj_b + 2 * CC) : l2b;
        const float* bo  = (blk < 256) ? out_proj_b : fuse_b;
        float* Wout = (blk < 256) ? WVO : M1;
        float* bout = (blk < 256) ? BVO : B2;

        r1[t] = Wo[(size_t)i * lda + t];
        __syncthreads();
        float s = 0.f;
        #pragma unroll 8
        for (int j = 0; j < CC; j++) s += r1[j] * Wv[j * CC + t];
        Wout[i * CC + t] = s;
        r2[t] = r1[t] * bv[t];
        __syncthreads();
        for (int o = 128; o > 0; o >>= 1) {
            if (t < o) r2[t] += r2[t + o];
            __syncthreads();
        }
        if (t == 0) bout[i] = r2[0] + bo[i];
    } else if (blk < 768) {
        const int i = blk - 512;
        const float fw = fuse_w[(size_t)i * 2 * CC + t];
        const __half hv = __float2half(node_w[t] * fw);
        WFh[i * CC + t] = hv;
        r1[t] = __half2float(hv);
        r2[t] = node_b[t] * fw;
        __syncthreads();
        for (int o = 128; o > 0; o >>= 1) {
            if (t < o) { r1[t] += r1[t + o]; r2[t] += r2[t + o]; }
            __syncthreads();
        }
        if (t == 0) { U[i] = r1[0]; V[i] = r2[0]; }
    } else if (blk < 768 + PP) {
        const int p = blk - 768;
        __shared__ int sb[2];
        if (t < 2) {
            int target = p + t;
            int lo = 0, hi = n;
            while (lo < hi) {
                int mid = (lo + hi) >> 1;
                if (batch[mid] < target) lo = mid + 1; else hi = mid;
            }
            sb[t] = lo;
        }
        __syncthreads();
        const int start = sb[0], end = sb[1];
        float s0 = 0.f, s1 = 0.f, s2 = 0.f, s3 = 0.f;
        int r = start;
        for (; r + 4 <= end; r += 4) {
            s0 += dg[(size_t)(r + 0) * CC + t];
            s1 += dg[(size_t)(r + 1) * CC + t];
            s2 += dg[(size_t)(r + 2) * CC + t];
            s3 += dg[(size_t)(r + 3) * CC + t];
        }
        for (; r < end; r++) s0 += dg[(size_t)r * CC + t];
        float s = (s0 + s1) + (s2 + s3);
        const int cnt = end - start;
        float mv = (cnt > 0) ? s / (float)cnt : 0.f;

        r1[t] = mv; __syncthreads();
        for (int o = 128; o > 0; o >>= 1) { if (t < o) r1[t] += r1[t + o]; __syncthreads(); }
        const float mu = r1[0] * (1.f / CC);
        __syncthreads();
        r1[t] = mv * mv; __syncthreads();
        for (int o = 128; o > 0; o >>= 1) { if (t < o) r1[t] += r1[t + o]; __syncthreads(); }
        const float var = r1[0] * (1.f / CC) - mu * mu;
        const float rstd = rsqrtf(var + 1e-5f);
        G[(size_t)p * CC + t] = (mv - mu) * rstd * dgw[t] + dgb[t];
    } else {
        const int row = (blk - 768 - PP) * 8 + (t >> 5);
        const int lane = t & 31;
        const float4* rp = orig4 + (size_t)row * 64;
        const float4 a = rp[lane], b = rp[lane + 32];
        float s  = (a.x + a.y) + (a.z + a.w) + (b.x + b.y) + (b.z + b.w);
        float s2 = a.x*a.x + a.y*a.y + a.z*a.z + a.w*a.w
                 + b.x*b.x + b.y*b.y + b.z*b.z + b.w*b.w;
        #pragma unroll
        for (int o = 16; o > 0; o >>= 1) {
            s  += __shfl_xor_sync(0xFFFFFFFFu, s,  o);
            s2 += __shfl_xor_sync(0xFFFFFFFFu, s2, o);
        }
        __half2 h0 = __floats2half2_rn(a.x, a.y), h1 = __floats2half2_rn(a.z, a.w);
        __half2 h2 = __floats2half2_rn(b.x, b.y), h3 = __floats2half2_rn(b.z, b.w);
        uint2* op = reinterpret_cast<uint2*>(OH + (size_t)row * CC);
        op[lane]      = make_uint2(*(uint32_t*)&h0, *(uint32_t*)&h1);
        op[lane + 32] = make_uint2(*(uint32_t*)&h2, *(uint32_t*)&h3);
        if (lane == 0) {
            const float m = s * (1.f / CC);
            MU[row] = m;
            RS[row] = rsqrtf(s2 * (1.f / CC) - m * m + 1e-5f);
        }
    }
}

// ---------------- warp-per-row LayerNorm (P rows) ----------------
__global__ void ln_rows(const float* __restrict__ in, const float* __restrict__ w,
                        const float* __restrict__ b, float* __restrict__ out, int rows)
{
    const int warp = blockIdx.x * (blockDim.x >> 5) + (threadIdx.x >> 5);
    if (warp >= rows) return;
    const int lane = threadIdx.x & 31;
    const float* rp = in + (size_t)warp * CC;
    float v[8];
    float s = 0.f, s2 = 0.f;
    #pragma unroll
    for (int i = 0; i < 8; i++) {
        v[i] = rp[lane + 32 * i];
        s  += v[i];
        s2 += v[i] * v[i];
    }
    #pragma unroll
    for (int o = 16; o > 0; o >>= 1) {
        s  += __shfl_xor_sync(0xFFFFFFFFu, s,  o);
        s2 += __shfl_xor_sync(0xFFFFFFFFu, s2, o);
    }
    const float mu  = s * (1.f / CC);
    const float var = s2 * (1.f / CC) - mu * mu;
    const float rstd = rsqrtf(var + 1e-5f);
    float* op = out + (size_t)warp * CC;
    #pragma unroll
    for (int i = 0; i < 8; i++) {
        const int c = lane + 32 * i;
        op[c] = (v[i] - mu) * rstd * w[c] + b[c];
    }
}

// ---------------- small tf32 wmma GEMM (unchanged, passing) ----------------
constexpr int BM = 128, BN = 64, BK = 32;
constexpr int LA = BK + 4;
constexpr int LC = BN + 4;

template<bool RELU, bool CAT>
__global__ __launch_bounds__(256)
void gemm_small(const float* __restrict__ A1, const float* __restrict__ B1, int ldb1,
                const float* __restrict__ A2, const float* __restrict__ B2x, int ldb2,
                float* __restrict__ C, const float* __restrict__ bias)
{
    __shared__ __align__(16) float smem[BM * LC];
    float* As = smem;
    float* Bs = smem + BM * LA;

    const int tid = threadIdx.x;
    const int warpId = tid >> 5;
    const int wm = warpId & 3;
    const int wn = warpId >> 2;
    const size_t gm = (size_t)blockIdx.y * BM;
    const int gn = blockIdx.x * BN;

    wmma::fragment<wmma::accumulator, 16, 16, 8, float> acc[2][2];
    #pragma unroll
    for (int i = 0; i < 2; i++)
        #pragma unroll
        for (int j = 0; j < 2; j++)
            wmma::fill_fragment(acc[i][j], 0.0f);

    const int lr = tid >> 3;
    const int lc = (tid & 7) << 2;
    const int KTOT = CAT ? 2 * CC : CC;

    for (int kt = 0; kt < KTOT; kt += BK) {
        const bool second = CAT && (kt >= CC);
        const float* A = second ? A2 : A1;
        const float* B = second ? B2x : B1;
        const int ldb = second ? ldb2 : ldb1;
        const int k0 = second ? kt - CC : kt;
        __syncthreads();
        #pragma unroll
        for (int p = 0; p < 4; p++) {
            const int r = lr + 32 * p;
            float4 v = *reinterpret_cast<const float4*>(A + (gm + r) * CC + k0 + lc);
            v.x = wmma::__float_to_tf32(v.x); v.y = wmma::__float_to_tf32(v.y);
            v.z = wmma::__float_to_tf32(v.z); v.w = wmma::__float_to_tf32(v.w);
            *reinterpret_cast<float4*>(&As[r * LA + lc]) = v;
        }
        #pragma unroll
        for (int p = 0; p < 2; p++) {
            const int r = lr + 32 * p;
            float4 v = *reinterpret_cast<const float4*>(B + (size_t)(gn + r) * ldb + k0 + lc);
            v.x = wmma::__float_to_tf32(v.x); v.y = wmma::__float_to_tf32(v.y);
            v.z = wmma::__float_to_tf32(v.z); v.w = wmma::__float_to_tf32(v.w);
            *reinterpret_cast<float4*>(&Bs[r * LA + lc]) = v;
        }
        __syncthreads();
        #pragma unroll
        for (int kk = 0; kk < BK; kk += 8) {
            wmma::fragment<wmma::matrix_a, 16, 16, 8, wmma::precision::tf32, wmma::row_major> af[2];
            wmma::fragment<wmma::matrix_b, 16, 16, 8, wmma::precision::tf32, wmma::col_major> bf[2];
            #pragma unroll
            for (int i = 0; i < 2; i++)
                wmma::load_matrix_sync(af[i], &As[(wm * 32 + 16 * i) * LA + kk], LA);
            #pragma unroll
            for (int j = 0; j < 2; j++)
                wmma::load_matrix_sync(bf[j], &Bs[(wn * 32 + 16 * j) * LA + kk], LA);
            #pragma unroll
            for (int i = 0; i < 2; i++)
                #pragma unroll
                for (int j = 0; j < 2; j++)
                    wmma::mma_sync(acc[i][j], af[i], bf[j], acc[i][j]);
        }
    }
    __syncthreads();
    #pragma unroll
    for (int i = 0; i < 2; i++)
        #pragma unroll
        for (int j = 0; j < 2; j++)
            wmma::store_matrix_sync(&smem[(wm * 32 + 16 * i) * LC + wn * 32 + 16 * j],
                                    acc[i][j], LC, wmma::mem_row_major);
    __syncthreads();

    const int ec = tid & 63;
    const int er = tid >> 6;
    #pragma unroll 4
    for (int r = er; r < BM; r += 4) {
        float c = smem[r * LC + ec] + bias[gn + ec];
        if (RELU) c = fmaxf(c, 0.0f);
        C[(gm + r) * CC + gn + ec] = c;
    }
}

// ================= BIG GEMM: PERSISTENT, B resident per SM =================
constexpr int SMB_B  = 0;                    // 8 chunks x 16384 = 131072
constexpr int SMB_A  = 131072;               // 2 stages x 32768 (8 chunks x 4096)
constexpr int SMB_U  = SMB_A + 65536;        // 196608
constexpr int SMB_V  = SMB_U  + 1024;
constexpr int SMB_NW = SMB_V  + 1024;
constexpr int SMB_NB = SMB_NW + 1024;
constexpr int SM_BIG = SMB_NB + 1024;        // 200704

__global__ __launch_bounds__(512)
void gemm_big_persist(const __half* __restrict__ OH,   // fp16 orig [N,256]
                      const __half* __restrict__ Bw,   // W' [256,256] fp16
                      const float* __restrict__ uvec, const float* __restrict__ vvec,
                      const int*   __restrict__ batch, const float* __restrict__ g2,
                      const float* __restrict__ nw, const float* __restrict__ nbv,
                      const float* __restrict__ mu_, const float* __restrict__ rs_,
                      float* __restrict__ out, int ntiles)
{
    extern __shared__ __align__(1024) char smc[];
    const uint32_t sbm = smem_u32(smc);
    const int tid  = threadIdx.x;
    const int wid  = tid >> 5;
    const int lane = tid & 31;
    const int wm = wid & 3;        // 4 row groups of 16
    const int wn = wid >> 2;       // 4 col groups of 64

    // params -> smem (visible after first barrier)
    if (tid < 256) {
        *reinterpret_cast<float*>(smc + SMB_U  + tid * 4) = uvec[tid];
        *reinterpret_cast<float*>(smc + SMB_V  + tid * 4) = vvec[tid];
        *reinterpret_cast<float*>(smc + SMB_NW + tid * 4) = nw[tid];
        *reinterpret_cast<float*>(smc + SMB_NB + tid * 4) = nbv[tid];
    }

    // B preload (once): 8192 16B transfers / 512 threads = 16 each
    #pragma unroll
    for (int i = 0; i < 16; i++) {
        const int idx = tid + 512 * i;        // 0..8191
        const int ch  = idx >> 10;            // k-chunk 0..7
        const int row = (idx & 1023) >> 2;    // 0..255 (output col)
        const int c16 = idx & 3;
        cp_async16(sbm + SMB_B + ch * 16384 + hswz(row, c16),
                   Bw + (size_t)row * CC + ch * 32 + c16 * 8);
    }

    // A tile loader: 2048 transfers / 512 = 4 each
    auto load_A = [&](int stage, int tile) {
        const size_t rb = (size_t)tile * 64;
        const uint32_t base = sbm + SMB_A + stage * 32768;
        #pragma unroll
        for (int i = 0; i < 4; i++) {
            const int idx = tid + 512 * i;    // 0..2047
            const int ch  = idx >> 8;         // 0..7
            const int row = (idx & 255) >> 2; // 0..63
            const int c16 = idx & 3;
            cp_async16(base + ch * 4096 + hswz(row, c16),
                       OH + (rb + row) * CC + ch * 32 + c16 * 8);
        }
    };

    load_A(0, blockIdx.x);
    CP_COMMIT();

    // ldsm lane-address components (validated R9-R11)
    const int aR = lane & 15;
    const int aC = lane >> 4;
    const int bR = ((lane >> 4) << 3) + (lane & 7);
    const int bC = (lane >> 3) & 1;

    const float* su  = reinterpret_cast<const float*>(smc + SMB_U);
    const float* sv  = reinterpret_cast<const float*>(smc + SMB_V);
    const float* sw  = reinterpret_cast<const float*>(smc + SMB_NW);
    const float* sbb = reinterpret_cast<const float*>(smc + SMB_NB);

    int it = 0;
    for (int t = blockIdx.x; t < ntiles; t += gridDim.x, it++) {
        CP_WAIT(0);
        __syncthreads();                       // tile t resident (and B on it==0)

        const int tn = t + gridDim.x;
        if (tn < ntiles) { load_A((it + 1) & 1, tn); CP_COMMIT(); }

        const uint32_t ast = sbm + SMB_A + (it & 1) * 32768;
        float acc[8][4];
        #pragma unroll
        for (int j = 0; j < 8; j++)
            #pragma unroll
            for (int e = 0; e < 4; e++) acc[j][e] = 0.f;

        #pragma unroll
        for (int kt = 0; kt < 8; kt++) {
            const uint32_t ab = ast + kt * 4096;
            const uint32_t bb = sbm + SMB_B + kt * 16384;
            #pragma unroll
            for (int kk = 0; kk < 2; kk++) {
                uint32_t av[4];
                ldsm4(av[0], av[1], av[2], av[3],
                      ab + hswz(wm * 16 + aR, kk * 2 + aC));
                uint32_t bv[4][4];
                #pragma unroll
                for (int nb = 0; nb < 4; nb++)
                    ldsm4(bv[nb][0], bv[nb][1], bv[nb][2], bv[nb][3],
                          bb + hswz(wn * 64 + nb * 16 + bR, kk * 2 + bC));
                #pragma unroll
                for (int nb = 0; nb < 4; nb++) {
                    mma_f16(acc[nb * 2 + 0], av[0], av[1], av[2], av[3],
                            bv[nb][0], bv[nb][1]);
                    mma_f16(acc[nb * 2 + 1], av[0], av[1], av[2], av[3],
                            bv[nb][2], bv[nb][3]);
                }
            }
        }

        // ---- direct-STG fused epilogue (residual from resident A stage) ----
        const size_t rowbase = (size_t)t * 64;
        #pragma unroll
        for (int rh = 0; rh < 2; rh++) {
            const int r = wm * 16 + (lane >> 2) + rh * 8;   // 0..63
            const size_t row = rowbase + r;
            const float m = __ldg(mu_ + row), rsv = __ldg(rs_ + row);
            const float mrs = m * rsv;
            const float* g2row = g2 + (size_t)__ldg(batch + row) * CC;
            #pragma unroll
            for (int nj = 0; nj < 8; nj++) {
                const int c = wn * 64 + nj * 8 + (lane & 3) * 2;
                const float2 g = *reinterpret_cast<const float2*>(g2row + c);
                float v0 = acc[nj][rh * 2 + 0] * rsv - mrs * su[c]     + sv[c]     + g.x;
                float v1 = acc[nj][rh * 2 + 1] * rsv - mrs * su[c + 1] + sv[c + 1] + g.y;
                v0 = fmaxf(v0, 0.f);
                v1 = fmaxf(v1, 0.f);
                const __half2 oh2 = *reinterpret_cast<const __half2*>(
                    smc + (ast - sbm) + (c >> 5) * 4096 + hswz(r, (c & 31) >> 3) + (c & 7) * 2);
                v0 += (__half2float(oh2.x) - m) * rsv * sw[c]     + sbb[c];
                v1 += (__half2float(oh2.y) - m) * rsv * sw[c + 1] + sbb[c + 1];
                *reinterpret_cast<float2*>(out + row * CC + c) = make_float2(v0, v1);
            }
        }
        // next iteration's top __syncthreads orders the stage overwrite
        // (first issued at t+2) after this epilogue's smem reads.
    }
}

// ---------------- launcher ----------------
extern "C" void kernel_launch(void* const* d_in, const int* in_sizes, int n_in,
                              void* d_out, int out_size)
{
    const float* orig       = (const float*)d_in[0];
    const float* dgf        = (const float*)d_in[1];
    const float* node_w     = (const float*)d_in[2];
    const float* node_b     = (const float*)d_in[3];
    const float* dg_w       = (const float*)d_in[4];
    const float* dg_b       = (const float*)d_in[5];
    const float* in_proj_w  = (const float*)d_in[6];
    const float* in_proj_b  = (const float*)d_in[7];
    const float* out_proj_w = (const float*)d_in[8];
    const float* out_proj_b = (const float*)d_in[9];
    const float* ffn_w      = (const float*)d_in[10];
    const float* ffn_b      = (const float*)d_in[11];
    const float* l1w        = (const float*)d_in[12];
    const float* l1b        = (const float*)d_in[13];
    const float* l2w        = (const float*)d_in[14];
    const float* l2b        = (const float*)d_in[15];
    const float* fuse_w     = (const float*)d_in[16];
    const float* fuse_b     = (const float*)d_in[17];
    const int*   batch      = (const int*)d_in[18];
    const int n = in_sizes[0] / CC;   // 262144

    float *G, *ATT, *Y, *H, *G2, *WVO, *BVO, *M1, *B2, *U, *V, *MU, *RS;
    __half *WFh, *OH;
    cudaGetSymbolAddress((void**)&G,   g_G);
    cudaGetSymbolAddress((void**)&ATT, g_ATT);
    cudaGetSymbolAddress((void**)&Y,   g_Y);
    cudaGetSymbolAddress((void**)&H,   g_H);
    cudaGetSymbolAddress((void**)&G2,  g_G2);
    cudaGetSymbolAddress((void**)&WVO, g_WVO);
    cudaGetSymbolAddress((void**)&BVO, g_BVO);
    cudaGetSymbolAddress((void**)&M1,  g_M1);
    cudaGetSymbolAddress((void**)&B2,  g_B2);
    cudaGetSymbolAddress((void**)&WFh, g_WFh);
    cudaGetSymbolAddress((void**)&U,   g_U);
    cudaGetSymbolAddress((void**)&V,   g_V);
    cudaGetSymbolAddress((void**)&OH,  g_OH);
    cudaGetSymbolAddress((void**)&MU,  g_MU);
    cudaGetSymbolAddress((void**)&RS,  g_RS);

    // one-time setup: keep the graph-capture path free of non-launch CUDA calls
    static int smCount = 0;
    if (smCount == 0) {
        cudaFuncSetAttribute(gemm_big_persist,
                             cudaFuncAttributeMaxDynamicSharedMemorySize, SM_BIG);
        int v = 148;
        cudaDeviceGetAttribute(&v, cudaDevAttrMultiProcessorCount, 0);
        smCount = (v > 0) ? v : 148;
    }

    const dim3 sg(CC / BN, PP / BM);   // (4, 32)
    const int ntiles = n / 64;         // 4096

    // 0: precomputes + segment-mean/LN + orig->fp16 prep
    fused_pre_seg<<<768 + PP + n / 8, 256>>>(
        out_proj_w, in_proj_w, in_proj_b, out_proj_b,
        fuse_w, l2w, l2b, fuse_b, node_w, node_b,
        dgf, batch, n, dg_w, dg_b, (const float4*)orig,
        WVO, BVO, M1, B2, WFh, U, V, G, OH, MU, RS);
    // 1: ATT = G @ WVO.T + BVO
    gemm_small<false, false><<<sg, 256>>>(G, WVO, CC, nullptr, nullptr, 0, ATT, BVO);
    // 2: Y = LN(ATT)
    ln_rows<<<PP / 8, 256>>>(ATT, ffn_w, ffn_b, Y, PP);
    // 3: H = relu(Y @ l1w.T + l1b)
    gemm_small<true, false><<<sg, 256>>>(Y, l1w, CC, nullptr, nullptr, 0, H, l1b);
    // 4: G2 = H @ M1.T + ATT @ Wf2.T + B2
    gemm_small<false, true><<<sg, 256>>>(H, M1, CC, ATT, fuse_w + CC, 2 * CC, G2, B2);
    // 5: big fused node GEMM — persistent, B resident per SM
    gemm_big_persist<<<smCount, 512, SM_BIG>>>(
        OH, WFh, U, V, batch, G2, node_w, node_b, MU, RS, (float*)d_out, ntiles);
}